// round 1
// baseline (speedup 1.0000x reference)
#include <cuda_runtime.h>

// H_13048110646034: butterfly-permuted complex locally-connected layer.
// B=8, N=16384, R=16, P=4096, T=64 (=4R).
// Per block p: Y_re[b,:] = xr@Wrr[p] + xi@Wri[p]; Y_im[b,:] = xr@Wir[p] + xi@Wii[p]
// xr[b, j*16+r] = x[b, 0, perm[4p+j], r];  xi same with c=1.
// out[b, c, 4p + o/16, o%16] = Y[b,c,o]  (contiguous 64-float run per (b,c,p)).

#define B_  8
#define N_  16384
#define P_  4096
#define T_  64

__global__ __launch_bounds__(128, 12)
void butterfly_local_kernel(const float* __restrict__ x,
                            const float* __restrict__ Wrr,
                            const float* __restrict__ Wri,
                            const float* __restrict__ Wir,
                            const float* __restrict__ Wii,
                            const int*   __restrict__ perm,
                            float* __restrict__ out)
{
    const int p = blockIdx.x;
    const int t = threadIdx.x;               // 0..127

    __shared__ float xs[2][B_][T_];          // [c][b][i]
    __shared__ int   rows[4];

    if (t < 4) rows[t] = perm[p * 4 + t];
    __syncthreads();

    // Gather: 64 rows (b,c,j) x 16 floats = 256 float4 loads, 2 per thread.
    #pragma unroll
    for (int u = t; u < 256; u += 128) {
        const int f4  = u & 3;               // float4 index within 16-float row
        const int row = u >> 2;              // 0..63
        const int j   = row & 3;
        const int cb  = row >> 2;            // 0..15 = b*2 + c
        const int b   = cb >> 1;
        const int c   = cb & 1;
        const int n   = rows[j];
        const float4 v = *(const float4*)&x[(((size_t)(b * 2 + c) * N_) + n) * 16 + f4 * 4];
        *(float4*)&xs[c][b][j * 16 + f4 * 4] = v;
    }
    __syncthreads();

    const int og = t & 15;                   // output quad 0..15
    const int b  = t >> 4;                   // batch 0..7

    const size_t wbase = (size_t)p * (T_ * T_);
    const float4* __restrict__ wrr = (const float4*)(Wrr + wbase) + og;
    const float4* __restrict__ wri = (const float4*)(Wri + wbase) + og;
    const float4* __restrict__ wir = (const float4*)(Wir + wbase) + og;
    const float4* __restrict__ wii = (const float4*)(Wii + wbase) + og;

    float4 aR = make_float4(0.f, 0.f, 0.f, 0.f);
    float4 aI = make_float4(0.f, 0.f, 0.f, 0.f);

    #pragma unroll 16
    for (int i = 0; i < T_; i++) {
        const float xr = xs[0][b][i];
        const float xi = xs[1][b][i];
        const float4 wa = wrr[i * 16];
        const float4 wb = wri[i * 16];
        const float4 wc = wir[i * 16];
        const float4 wd = wii[i * 16];
        aR.x = fmaf(xr, wa.x, aR.x); aR.x = fmaf(xi, wb.x, aR.x);
        aR.y = fmaf(xr, wa.y, aR.y); aR.y = fmaf(xi, wb.y, aR.y);
        aR.z = fmaf(xr, wa.z, aR.z); aR.z = fmaf(xi, wb.z, aR.z);
        aR.w = fmaf(xr, wa.w, aR.w); aR.w = fmaf(xi, wb.w, aR.w);
        aI.x = fmaf(xr, wc.x, aI.x); aI.x = fmaf(xi, wd.x, aI.x);
        aI.y = fmaf(xr, wc.y, aI.y); aI.y = fmaf(xi, wd.y, aI.y);
        aI.z = fmaf(xr, wc.z, aI.z); aI.z = fmaf(xi, wd.z, aI.z);
        aI.w = fmaf(xr, wc.w, aI.w); aI.w = fmaf(xi, wd.w, aI.w);
    }

    // out offset for (b, c, p): ((b*2 + c)*N + 4p)*16 + og*4
    const size_t reOff = (((size_t)(b * 2 + 0) * N_) + 4 * (size_t)p) * 16 + og * 4;
    const size_t imOff = (((size_t)(b * 2 + 1) * N_) + 4 * (size_t)p) * 16 + og * 4;
    *(float4*)&out[reOff] = aR;
    *(float4*)&out[imOff] = aI;
}

extern "C" void kernel_launch(void* const* d_in, const int* in_sizes, int n_in,
                              void* d_out, int out_size)
{
    const float* x    = (const float*)d_in[0];
    const float* Wrr  = (const float*)d_in[1];
    const float* Wri  = (const float*)d_in[2];
    const float* Wir  = (const float*)d_in[3];
    const float* Wii  = (const float*)d_in[4];
    const int*   perm = (const int*)d_in[5];
    float* out = (float*)d_out;

    butterfly_local_kernel<<<P_, 128>>>(x, Wrr, Wri, Wir, Wii, perm, out);
}